// round 14
// baseline (speedup 1.0000x reference)
#include <cuda_runtime.h>
#include <cuda_fp16.h>
#include <math.h>

#define NSEQ 2048
#define HDIM 1024
#define NHEAD 16
#define DH 64
#define S2 1024        // 2 * span
#define SPAN 512
#define INV_SCALE 0.0721687836487032f   // 1/sqrt(64*3)

// ---------------- scratch (device globals; no allocations allowed) ----------
__device__ __half g_Q[NHEAD * NSEQ * DH];            // fp16 (MMA-native)
__device__ __half g_K[NHEAD * NSEQ * DH];
__device__ __half g_V[NHEAD * NSEQ * DH];
__device__ __half g_PosK[NHEAD * S2 * DH];
__device__ __half g_PosQ[NHEAD * S2 * DH];
__device__ __half g_c2p[(size_t)NHEAD * NSEQ * S2];   // 67 MB (fp16)
__device__ __half g_p2c[(size_t)NHEAD * NSEQ * S2];   // 67 MB (fp16)
__device__ __half g_scH[(size_t)NHEAD * NSEQ * NSEQ]; // 134 MB tile-ref'd exp probs
__device__ unsigned g_maskBits[NSEQ * (NSEQ / 32)];  // 512 KB packed mask
__device__ float g_statM[(size_t)NHEAD * NSEQ * 32]; // per-row per-halftile max
__device__ float g_statL[(size_t)NHEAD * NSEQ * 32]; // per-row per-halftile sumexp
__device__ float g_rowM  [NHEAD * NSEQ];
__device__ float g_rowInv[NHEAD * NSEQ];

// ------------------------------- fp16 mma -----------------------------------
__device__ __forceinline__ unsigned f2h2(float a, float b) {
    __half2 h = __floats2half2_rn(a, b);
    return *reinterpret_cast<unsigned*>(&h);
}

__device__ __forceinline__ unsigned smem_u32(const void* p) {
    return (unsigned)__cvta_generic_to_shared(p);
}

__device__ __forceinline__ void ldsm_x4(unsigned& r0, unsigned& r1,
                                        unsigned& r2, unsigned& r3, unsigned addr) {
    asm volatile("ldmatrix.sync.aligned.m8n8.x4.shared.b16 {%0,%1,%2,%3}, [%4];"
                 : "=r"(r0), "=r"(r1), "=r"(r2), "=r"(r3) : "r"(addr));
}

__device__ __forceinline__ void mma_f16(float (&d)[4],
                                        unsigned a0, unsigned a1, unsigned a2, unsigned a3,
                                        unsigned b0, unsigned b1) {
    asm volatile(
        "mma.sync.aligned.m16n8k16.row.col.f32.f16.f16.f32 "
        "{%0,%1,%2,%3}, {%4,%5,%6,%7}, {%8,%9}, {%0,%1,%2,%3};"
        : "+f"(d[0]), "+f"(d[1]), "+f"(d[2]), "+f"(d[3])
        : "r"(a0), "r"(a1), "r"(a2), "r"(a3), "r"(b0), "r"(b1));
}

// One BK=16 step of m16n8k16, fragments via ldmatrix.x4.
// Operand layout [row][kpair] (half2 packed). Strides ≡4 (mod 8) in 4-byte
// units for conflict-free LDSM (12 and 36 both qualify).
template <int MT, int NT>
__device__ __forceinline__ void mma16(const unsigned* __restrict__ As, int lda,
                                      const unsigned* __restrict__ Bs, int ldb,
                                      int kp0, int wm0, int wn0, int lane,
                                      float (&acc)[MT][NT][4]) {
    const int j = lane >> 3, r = lane & 7;
    unsigned a[MT][4];
#pragma unroll
    for (int mt = 0; mt < MT; mt++) {
        unsigned addr = smem_u32(
            &As[(size_t)(wm0 + mt * 16 + (j & 1) * 8 + r) * lda + kp0 + (j >> 1) * 4]);
        ldsm_x4(a[mt][0], a[mt][1], a[mt][2], a[mt][3], addr);
    }
    unsigned b0[NT], b1[NT];
#pragma unroll
    for (int i = 0; i < NT / 2; i++) {
        unsigned addr = smem_u32(
            &Bs[(size_t)(wn0 + (2 * i + (j >> 1)) * 8 + r) * ldb + kp0 + (j & 1) * 4]);
        ldsm_x4(b0[2 * i], b1[2 * i], b0[2 * i + 1], b1[2 * i + 1], addr);
    }
#pragma unroll
    for (int nt = 0; nt < NT; nt++)
#pragma unroll
        for (int mt = 0; mt < MT; mt++)
            mma_f16(acc[mt][nt], a[mt][0], a[mt][1], a[mt][2], a[mt][3], b0[nt], b1[nt]);
}

// Variant for pv: A via ldmatrix, B via scalar LDS (B stride 13 not LDSM-safe).
template <int NT>
__device__ __forceinline__ void mma16_bs(const unsigned* __restrict__ As, int lda,
                                         const unsigned* __restrict__ Bs, int ldb,
                                         int wm0, int lane,
                                         float (&acc)[1][NT][4]) {
    const int j = lane >> 3, r = lane & 7;
    const int kq = lane & 3, rq = lane >> 2;
    unsigned a[4];
    {
        unsigned addr = smem_u32(
            &As[(size_t)(wm0 + (j & 1) * 8 + r) * lda + (j >> 1) * 4]);
        ldsm_x4(a[0], a[1], a[2], a[3], addr);
    }
#pragma unroll
    for (int nt = 0; nt < NT; nt++) {
        const int n = nt * 8 + rq;
        unsigned b0 = Bs[(size_t)n * ldb + kq];
        unsigned b1 = Bs[(size_t)n * ldb + kq + 4];
        mma_f16(acc[0][nt], a[0], a[1], a[2], a[3], b0, b1);
    }
}

// ---------------------------------------------------------------------------
// K0: pack attention mask into bits
// ---------------------------------------------------------------------------
__global__ void __launch_bounds__(256) pack_kernel(const int* __restrict__ mask) {
    int gid = blockIdx.x * 256 + threadIdx.x;
    unsigned b = __ballot_sync(0xffffffffu, mask[gid] != 0);
    if ((gid & 31) == 0) g_maskBits[gid >> 5] = b;
}

// ---------------------------------------------------------------------------
// K1: QKV projection. M=2048, N=3072, K=1024. BM=BN=128, BK=16, double-buffered.
// ---------------------------------------------------------------------------
#define LDK 12   // 8 kpairs + 4 pad (half2 units); 12 ≡ 4 (mod 8) -> LDSM-safe
__global__ void __launch_bounds__(256) qkv_kernel(const float* __restrict__ hidden,
                                                  const float* __restrict__ W,
                                                  const float* __restrict__ qb,
                                                  const float* __restrict__ vb) {
    __shared__ unsigned As[2][128 * LDK];
    __shared__ unsigned Bs[2][128 * LDK];
    const int t = threadIdx.x, lane = t & 31, wid = t >> 5;
    const int wm0 = (wid >> 1) * 32, wn0 = (wid & 1) * 64;
    const int m0 = blockIdx.y * 128, n0 = blockIdx.x * 128;
    const int r0 = t >> 2, g = t & 3;

    float acc[2][8][4];
#pragma unroll
    for (int mt = 0; mt < 2; mt++)
#pragma unroll
        for (int nt = 0; nt < 8; nt++)
#pragma unroll
            for (int e = 0; e < 4; e++) acc[mt][nt][e] = 0.0f;

    float4 ra[2], rb[2];
    auto ldg = [&](int kt) {
        ra[0] = *(const float4*)&hidden[(size_t)(m0 + r0) * HDIM + kt + g * 4];
        ra[1] = *(const float4*)&hidden[(size_t)(m0 + r0 + 64) * HDIM + kt + g * 4];
        rb[0] = *(const float4*)&W[(size_t)(n0 + r0) * HDIM + kt + g * 4];
        rb[1] = *(const float4*)&W[(size_t)(n0 + r0 + 64) * HDIM + kt + g * 4];
    };
    auto sts = [&](int buf) {
#pragma unroll
        for (int half = 0; half < 2; half++) {
            int r = r0 + half * 64;
            As[buf][r * LDK + g * 2]     = f2h2(((float*)ra)[half * 4 + 0], ((float*)ra)[half * 4 + 1]);
            As[buf][r * LDK + g * 2 + 1] = f2h2(((float*)ra)[half * 4 + 2], ((float*)ra)[half * 4 + 3]);
            Bs[buf][r * LDK + g * 2]     = f2h2(((float*)rb)[half * 4 + 0], ((float*)rb)[half * 4 + 1]);
            Bs[buf][r * LDK + g * 2 + 1] = f2h2(((float*)rb)[half * 4 + 2], ((float*)rb)[half * 4 + 3]);
        }
    };

    ldg(0); sts(0);
    const int nt_tiles = HDIM / 16;
    for (int kt = 0; kt < nt_tiles; kt++) {
        __syncthreads();
        if (kt + 1 < nt_tiles) ldg((kt + 1) * 16);
        mma16<2, 8>(As[kt & 1], LDK, Bs[kt & 1], LDK, 0, wm0, wn0, lane, acc);
        if (kt + 1 < nt_tiles) sts((kt + 1) & 1);
    }

    const int kq = lane & 3, rq = lane >> 2;
#pragma unroll
    for (int mt = 0; mt < 2; mt++)
#pragma unroll
        for (int nt = 0; nt < 8; nt++)
#pragma unroll
            for (int h2 = 0; h2 < 2; h2++) {
                int m  = m0 + wm0 + mt * 16 + rq + h2 * 8;
                int cg = n0 + wn0 + nt * 8 + kq * 2;
                int head = cg / 192;
                int jj = cg - head * 192;
                float v0 = acc[mt][nt][h2 * 2], v1 = acc[mt][nt][h2 * 2 + 1];
                if (jj < 64) {
                    v0 = (v0 + qb[head * 64 + jj]) * INV_SCALE;
                    v1 = (v1 + qb[head * 64 + jj + 1]) * INV_SCALE;
                    *(__half2*)&g_Q[(size_t)(head * NSEQ + m) * DH + jj] =
                        __floats2half2_rn(v0, v1);
                } else if (jj < 128) {
                    *(__half2*)&g_K[(size_t)(head * NSEQ + m) * DH + jj - 64] =
                        __floats2half2_rn(v0, v1);
                } else {
                    v0 += vb[head * 64 + jj - 128];
                    v1 += vb[head * 64 + jj - 127];
                    *(__half2*)&g_V[(size_t)(head * NSEQ + m) * DH + jj - 128] =
                        __floats2half2_rn(v0, v1);
                }
            }
}

// ---------------------------------------------------------------------------
// K2: position projections. z=0: PosK, z=1: PosQ. M=N=K=1024.
// ---------------------------------------------------------------------------
__global__ void __launch_bounds__(256) pos_kernel(const float* __restrict__ rel,
                                                  const float* __restrict__ Wk,
                                                  const float* __restrict__ Wq,
                                                  const float* __restrict__ bias) {
    __shared__ unsigned As[2][128 * LDK];
    __shared__ unsigned Bs[2][128 * LDK];
    const int which = blockIdx.z;
    const float* W = which == 0 ? Wk : Wq;
    const int t = threadIdx.x, lane = t & 31, wid = t >> 5;
    const int wm0 = (wid >> 1) * 32, wn0 = (wid & 1) * 64;
    const int m0 = blockIdx.y * 128, n0 = blockIdx.x * 128;
    const int r0 = t >> 2, g = t & 3;

    float acc[2][8][4];
#pragma unroll
    for (int mt = 0; mt < 2; mt++)
#pragma unroll
        for (int nt = 0; nt < 8; nt++)
#pragma unroll
            for (int e = 0; e < 4; e++) acc[mt][nt][e] = 0.0f;

    float4 ra[2], rb[2];
    auto ldg = [&](int kt) {
        ra[0] = *(const float4*)&rel[(size_t)(m0 + r0) * HDIM + kt + g * 4];
        ra[1] = *(const float4*)&rel[(size_t)(m0 + r0 + 64) * HDIM + kt + g * 4];
        rb[0] = *(const float4*)&W[(size_t)(n0 + r0) * HDIM + kt + g * 4];
        rb[1] = *(const float4*)&W[(size_t)(n0 + r0 + 64) * HDIM + kt + g * 4];
    };
    auto sts = [&](int buf) {
#pragma unroll
        for (int half = 0; half < 2; half++) {
            int r = r0 + half * 64;
            As[buf][r * LDK + g * 2]     = f2h2(((float*)ra)[half * 4 + 0], ((float*)ra)[half * 4 + 1]);
            As[buf][r * LDK + g * 2 + 1] = f2h2(((float*)ra)[half * 4 + 2], ((float*)ra)[half * 4 + 3]);
            Bs[buf][r * LDK + g * 2]     = f2h2(((float*)rb)[half * 4 + 0], ((float*)rb)[half * 4 + 1]);
            Bs[buf][r * LDK + g * 2 + 1] = f2h2(((float*)rb)[half * 4 + 2], ((float*)rb)[half * 4 + 3]);
        }
    };

    ldg(0); sts(0);
    const int nt_tiles = HDIM / 16;
    for (int kt = 0; kt < nt_tiles; kt++) {
        __syncthreads();
        if (kt + 1 < nt_tiles) ldg((kt + 1) * 16);
        mma16<2, 8>(As[kt & 1], LDK, Bs[kt & 1], LDK, 0, wm0, wn0, lane, acc);
        if (kt + 1 < nt_tiles) sts((kt + 1) & 1);
    }

    const int kq = lane & 3, rq = lane >> 2;
#pragma unroll
    for (int mt = 0; mt < 2; mt++)
#pragma unroll
        for (int nt = 0; nt < 8; nt++)
#pragma unroll
            for (int h2 = 0; h2 < 2; h2++) {
                int s  = m0 + wm0 + mt * 16 + rq + h2 * 8;
                int cc = n0 + wn0 + nt * 8 + kq * 2;
                int head = cc >> 6, d = cc & 63;
                float v0 = acc[mt][nt][h2 * 2], v1 = acc[mt][nt][h2 * 2 + 1];
                if (which == 0) {
                    *(__half2*)&g_PosK[(size_t)(head * S2 + s) * DH + d] =
                        __floats2half2_rn(v0, v1);
                } else {
                    v0 = (v0 + bias[cc]) * INV_SCALE;
                    v1 = (v1 + bias[cc + 1]) * INV_SCALE;
                    *(__half2*)&g_PosQ[(size_t)(head * S2 + s) * DH + d] =
                        __floats2half2_rn(v0, v1);
                }
            }
}

// ---------------------------------------------------------------------------
// K=64 tile fill from fp16 source: pure copy into [row][kpair], LDK64=36.
// ---------------------------------------------------------------------------
#define LDK64 36   // 32 kpairs + 4 pad; 36 ≡ 4 (mod 8) -> LDSM-safe
__device__ __forceinline__ void fill_k64h(const __half* __restrict__ src, int row0,
                                          unsigned* __restrict__ T, int t) {
#pragma unroll
    for (int i = 0; i < 4; i++) {
        int lin4 = i * 256 + t;           // 1024 uint4s (128 rows x 8)
        int r = lin4 >> 3, g = lin4 & 7;
        uint4 v = *(const uint4*)&src[(size_t)(row0 + r) * DH + g * 8];
        *(uint4*)&T[r * LDK64 + g * 4] = v;
    }
}

// Staging tile stride (uints): 68 -> STS banks 4*rq + kq, all 32 distinct.
#define LDO 68

// ---------------------------------------------------------------------------
// K3: raw relative scores -> fp16, smem-staged coalesced epilogue.
// ---------------------------------------------------------------------------
__global__ void __launch_bounds__(256) relsc_kernel() {
    extern __shared__ float sm[];
    unsigned* As = (unsigned*)sm;
    unsigned* Bs = (unsigned*)sm + 128 * LDK64;
    unsigned* Ot = (unsigned*)sm;            // reused after MMA (8704 <= 9216)
    const int z = blockIdx.z;
    const int h = z & 15, which = z >> 4;
    const int m0 = blockIdx.y * 128, n0 = blockIdx.x * 128;
    const __half* A = (which == 0 ? g_Q : g_K) + (size_t)h * NSEQ * DH;
    const __half* B = (which == 0 ? g_PosK : g_PosQ) + (size_t)h * S2 * DH;
    __half* O = (which == 0 ? g_c2p : g_p2c);

    const int t = threadIdx.x, lane = t & 31, wid = t >> 5;
    const int wm0 = (wid >> 1) * 32, wn0 = (wid & 1) * 64;

    fill_k64h(A, m0, As, t);
    fill_k64h(B, n0, Bs, t);
    __syncthreads();

    float acc[2][8][4];
#pragma unroll
    for (int mt = 0; mt < 2; mt++)
#pragma unroll
        for (int nt = 0; nt < 8; nt++)
#pragma unroll
            for (int e = 0; e < 4; e++) acc[mt][nt][e] = 0.0f;

#pragma unroll
    for (int s16 = 0; s16 < 4; s16++)
        mma16<2, 8>(As, LDK64, Bs, LDK64, s16 * 8, wm0, wn0, lane, acc);

    __syncthreads();   // operands consumed -> reuse as staging
    const int kq = lane & 3, rq = lane >> 2;
#pragma unroll
    for (int mt = 0; mt < 2; mt++)
#pragma unroll
        for (int nt = 0; nt < 8; nt++)
#pragma unroll
            for (int h2 = 0; h2 < 2; h2++) {
                int rm = wm0 + mt * 16 + rq + h2 * 8;
                int cn = (wn0 >> 1) + nt * 4 + kq;
                Ot[rm * LDO + cn] = f2h2(acc[mt][nt][h2 * 2], acc[mt][nt][h2 * 2 + 1]);
            }
    __syncthreads();
    // coalesced copy out: 128 rows x 16 uint4
#pragma unroll
    for (int i = 0; i < 8; i++) {
        int lin4 = i * 256 + t;
        int r = lin4 >> 4, c4 = (lin4 & 15) * 4;
        uint4 v = *(const uint4*)&Ot[r * LDO + c4];
        *(uint4*)&O[((size_t)(h * NSEQ + m0 + r)) * S2 + n0 + c4 * 2] = v;
    }
}

// ---------------------------------------------------------------------------
// K4: scores = QK^T + c2p + p2c + mask(bits) -> fp16 exp(s - m_tile) + stats.
// Fast path for fully-clamped tiles (bias separable).
// Band path: p2c staged as fp16 (stride 130 halves, conflict-free); c2p read
// DIRECTLY in the epilogue (quad-contiguous __ldg) — no fp32 G, no RMW.
// Probs staged in smem then stored coalesced.
// ---------------------------------------------------------------------------
#define LDP 130   // p2c staging stride in halves: 65 words ≡ 1 (mod 32)
__global__ void __launch_bounds__(256, 2) scores_kernel() {
    extern __shared__ float sm[];
    unsigned* As = (unsigned*)sm;
    unsigned* Bs = (unsigned*)sm + 128 * LDK64;
    __half*   P2s = (__half*)sm;                       // reuse As/Bs after MMA
    unsigned* Ot  = (unsigned*)sm + 2 * 128 * LDK64;   // prob staging
    float*    cE  = (float*)(Ot + 128 * LDO);
    float*    pE  = cE + 128;

    const int h  = blockIdx.z;
    const int m0 = blockIdx.y * 128, n0 = blockIdx.x * 128;
    const int d  = m0 - n0;
    const bool fast = (d >= 640) || (d <= -640);
    const int t = threadIdx.x, lane = t & 31, wid = t >> 5;
    const int wm0 = (wid >> 1) * 32, wn0 = (wid & 1) * 64;

    const __half* C2 = g_c2p + (size_t)h * NSEQ * S2;
    const __half* P2 = g_p2c + (size_t)h * NSEQ * S2;

    fill_k64h(g_Q + (size_t)h * NSEQ * DH, m0, As, t);
    fill_k64h(g_K + (size_t)h * NSEQ * DH, n0, Bs, t);
    if (fast) {
        const int col = (d >= 640) ? (S2 - 1) : 0;
        if (t < 128) cE[t] = __half2float(C2[(size_t)(m0 + t) * S2 + col]);
        else         pE[t - 128] = __half2float(P2[(size_t)(n0 + t - 128) * S2 + col]);
    }
    __syncthreads();

    float acc[2][8][4];
#pragma unroll
    for (int mt = 0; mt < 2; mt++)
#pragma unroll
        for (int nt = 0; nt < 8; nt++)
#pragma unroll
            for (int e = 0; e < 4; e++) acc[mt][nt][e] = 0.0f;

#pragma unroll
    for (int s16 = 0; s16 < 4; s16++)
        mma16<2, 8>(As, LDK64, Bs, LDK64, s16 * 8, wm0, wn0, lane, acc);

    if (!fast) {
        __syncthreads();   // operands consumed -> reuse as p2c staging
        // P2s[qi][jr] = p2c[n0+jr][idx(qi)] — global reads contiguous along qi
#pragma unroll
        for (int i = 0; i < 64; i++) {
            int lin = i * 256 + t;
            int jr = lin >> 7, qi = lin & 127;
            int idx = d + qi - jr + SPAN;
            idx = idx < 0 ? 0 : (idx > S2 - 1 ? S2 - 1 : idx);
            P2s[qi * LDP + jr] = P2[(size_t)(n0 + jr) * S2 + idx];
        }
        __syncthreads();
    }

    // epilogue: finalize, stage fp16 exp(s - m_tile) in smem, per-halftile stats
    const int kq = lane & 3, rq = lane >> 2;
    const int ht = blockIdx.x * 2 + (wn0 >> 6);
    const int wbase = (n0 + wn0) >> 5;
#pragma unroll
    for (int mt = 0; mt < 2; mt++)
#pragma unroll
        for (int h2 = 0; h2 < 2; h2++) {
            const int rm = wm0 + mt * 16 + rq + h2 * 8;
            const int q = m0 + rm;
            const unsigned mwA = g_maskBits[q * (NSEQ / 32) + wbase];
            const unsigned mwB = g_maskBits[q * (NSEQ / 32) + wbase + 1];
            const float ce = fast ? cE[rm] : 0.0f;
            float vals[16];
            float rmax = -INFINITY;
#pragma unroll
            for (int nt = 0; nt < 8; nt++) {
                int rn = wn0 + nt * 8 + kq * 2;
                float b0, b1;
                if (fast) {
                    b0 = ce + pE[rn]; b1 = ce + pE[rn + 1];
                } else {
                    int i0 = d + rm - rn + SPAN;
                    int i1 = i0 - 1;
                    i0 = i0 < 0 ? 0 : (i0 > S2 - 1 ? S2 - 1 : i0);
                    i1 = i1 < 0 ? 0 : (i1 > S2 - 1 ? S2 - 1 : i1);
                    unsigned pw = *(const unsigned*)&P2s[rm * LDP + rn];
                    float2 pf = __half22float2(*reinterpret_cast<__half2*>(&pw));
                    b0 = __half2float(__ldg(&C2[(size_t)q * S2 + i0])) + pf.x;
                    b1 = __half2float(__ldg(&C2[(size_t)q * S2 + i1])) + pf.y;
                }
                float v0 = acc[mt][nt][h2 * 2]     + b0;
                float v1 = acc[mt][nt][h2 * 2 + 1] + b1;
                unsigned w = (nt < 4) ? mwA : mwB;
                int bp = ((nt & 3) * 8) + kq * 2;
                if (!((w >> bp) & 1u))       v0 = -1e30f;
                if (!((w >> (bp + 1)) & 1u)) v1 = -1e30f;
                vals[nt * 2] = v0; vals[nt * 2 + 1] = v1;
                rmax = fmaxf(rmax, fmaxf(v0, v1));
            }
            rmax = fmaxf(rmax, __shfl_xor_sync(0xffffffffu, rmax, 1));
            rmax = fmaxf(rmax, __shfl_xor_sync(0xffffffffu, rmax, 2));
            float rsum = 0.0f;
#pragma unroll
            for (int nt = 0; nt < 8; nt++) {
                int cn = (wn0 >> 1) + nt * 4 + kq;
                float p0 = __expf(vals[nt * 2] - rmax);
                float p1 = __expf(vals[nt * 2 + 1] - rmax);
                rsum += p0 + p1;
                Ot[rm * LDO + cn] = f2h2(p0, p1);
            }
            rsum += __shfl_xor_sync(0xffffffffu, rsum, 1);
            rsum += __shfl_xor_sync(0xffffffffu, rsum, 2);
            if (kq == 0) {
                g_statM[((size_t)(h * NSEQ + q)) * 32 + ht] = rmax;
                g_statL[((size_t)(h * NSEQ + q)) * 32 + ht] = rsum;
            }
        }
    __syncthreads();
    // coalesced prob store: 128 rows x 16 uint4
#pragma unroll
    for (int i = 0; i < 8; i++) {
        int lin4 = i * 256 + t;
        int r = lin4 >> 4, c4 = (lin4 & 15) * 4;
        uint4 v = *(const uint4*)&Ot[r * LDO + c4];
        *(uint4*)&g_scH[((size_t)(h * NSEQ + m0 + r)) * NSEQ + n0 + c4 * 2] = v;
    }
}

// ---------------------------------------------------------------------------
// K5: combine per-halftile stats into row max / inv-sum
// ---------------------------------------------------------------------------
__global__ void __launch_bounds__(256) combine_kernel() {
    const int row = blockIdx.x * 256 + threadIdx.x;   // h*NSEQ + q
    const size_t b = (size_t)row * 32;
    float m = -INFINITY;
#pragma unroll
    for (int i = 0; i < 32; i++) m = fmaxf(m, g_statM[b + i]);
    float l = 0.0f;
#pragma unroll
    for (int i = 0; i < 32; i++) l += g_statL[b + i] * __expf(g_statM[b + i] - m);
    g_rowM[row]   = m;
    g_rowInv[row] = 1.0f / l;
}

// ---------------------------------------------------------------------------
// K6: PV, full K=2048, direct output write (normalization in corr).
// fp16 probs * per-(row, halftile) corr fused into the A fill.
// A fragments via ldmatrix (LDK=12 LDSM-safe); B scalar (LDKB=13).
// ---------------------------------------------------------------------------
#define LDKB 13   // B tile: 8 kpairs + 5 pad
__global__ void __launch_bounds__(256) pv_kernel(float* __restrict__ out) {
    __shared__ unsigned As[2][128 * LDK];
    __shared__ unsigned Bs[2][64 * LDKB];
    __shared__ float corr[128 * 32];    // [r][halftile]

    const int mt0 = blockIdx.x, h = blockIdx.y;
    const int m0 = mt0 * 128;
    const int t = threadIdx.x, lane = t & 31, wid = t >> 5;
    const int wm0 = wid * 16;
    const __half* Ag = g_scH + (size_t)h * NSEQ * NSEQ;
    const __half* Vg = g_V + (size_t)h * NSEQ * DH;

    for (int idx = t; idx < 128 * 32; idx += 256) {
        int r = idx >> 5, htl = idx & 31;
        int row = h * NSEQ + m0 + r;
        corr[idx] = __expf(g_statM[(size_t)row * 32 + htl] - g_rowM[row])
                    * g_rowInv[row];
    }
    __syncthreads();

    float acc[1][8][4];
#pragma unroll
    for (int nt = 0; nt < 8; nt++)
#pragma unroll
        for (int e = 0; e < 4; e++) acc[0][nt][e] = 0.0f;

    const int ra0 = t >> 1, ca = t & 1;         // A: 128 rows x 2 uint4/row
    const int kpB = (t >> 3) & 7, d8 = (t & 7) * 8;  // B: 64 active threads
    const bool bact = t < 64;
    uint4 pa, vb0, vb1;
    auto ldg = [&](int kt) {
        pa = *(const uint4*)&Ag[(size_t)(m0 + ra0) * NSEQ + kt + ca * 8];
        if (bact) {
            vb0 = *(const uint4*)&Vg[(size_t)(kt + 2 * kpB) * DH + d8];
            vb1 = *(const uint4*)&Vg[(size_t)(kt + 2 * kpB + 1) * DH + d8];
        }
    };
    auto sts = [&](int buf, int kt_idx) {
        __half2 c2 = __float2half2_rn(corr[ra0 * 32 + (kt_idx >> 2)]);
        const __half2* hp = (const __half2*)&pa;
#pragma unroll
        for (int e = 0; e < 4; e++) {
            __half2 v = __hmul2(hp[e], c2);
            As[buf][ra0 * LDK + ca * 4 + e] = *reinterpret_cast<unsigned*>(&v);
        }
        if (bact) {
            const unsigned* a0 = (const unsigned*)&vb0;
            const unsigned* a1 = (const unsigned*)&vb1;
#pragma unroll
            for (int e = 0; e < 4; e++) {
                Bs[buf][(d8 + 2 * e) * LDKB + kpB]     = __byte_perm(a0[e], a1[e], 0x5410);
                Bs[buf][(d8 + 2 * e + 1) * LDKB + kpB] = __byte_perm(a0[e], a1[e], 0x7632);
            }
        }
    };

    ldg(0); sts(0, 0);
    const int ntile = NSEQ / 16;   // 128
    for (int kt = 0; kt < ntile; kt++) {
        __syncthreads();
        if (kt + 1 < ntile) ldg((kt + 1) * 16);
        mma16_bs<8>(As[kt & 1], LDK, Bs[kt & 1], LDKB, wm0, lane, acc);
        if (kt + 1 < ntile) sts((kt + 1) & 1, kt + 1);
    }

    const int kq = lane & 3, rq = lane >> 2;
#pragma unroll
    for (int nt = 0; nt < 8; nt++)
#pragma unroll
        for (int h2 = 0; h2 < 2; h2++) {
            int m = m0 + wm0 + rq + h2 * 8;
            int n = nt * 8 + kq * 2;
            *(float2*)&out[(size_t)m * HDIM + h * DH + n] =
                make_float2(acc[0][nt][h2 * 2], acc[0][nt][h2 * 2 + 1]);
        }
}

// ---------------------------------------------------------------------------
extern "C" void kernel_launch(void* const* d_in, const int* in_sizes, int n_in,
                              void* d_out, int out_size) {
    const float* hidden   = (const float*)d_in[0];
    const int*   mask     = (const int*)  d_in[1];
    const float* rel_emb  = (const float*)d_in[3];
    const float* in_proj  = (const float*)d_in[4];
    const float* q_bias   = (const float*)d_in[5];
    const float* v_bias   = (const float*)d_in[6];
    const float* pos_w    = (const float*)d_in[7];
    const float* pos_q_w  = (const float*)d_in[8];
    const float* pos_q_b  = (const float*)d_in[9];
    float* out = (float*)d_out;

    const int relsc_smem  = 2 * 128 * LDK64 * 4;                     // 36864 B
    const int scores_smem = (2 * 128 * LDK64 + 128 * LDO + 256) * 4; // 72704 B
    cudaFuncSetAttribute(relsc_kernel, cudaFuncAttributeMaxDynamicSharedMemorySize,
                         relsc_smem);
    cudaFuncSetAttribute(scores_kernel, cudaFuncAttributeMaxDynamicSharedMemorySize,
                         scores_smem);

    // K0: pack mask bits
    pack_kernel<<<(NSEQ * NSEQ) / 256, 256>>>(mask);

    // K1: QKV projection (fp16 outputs)
    qkv_kernel<<<dim3(3072 / 128, 2048 / 128), 256>>>(hidden, in_proj, q_bias, v_bias);

    // K2: position projections (fp16 outputs)
    pos_kernel<<<dim3(HDIM / 128, S2 / 128, 2), 256>>>(rel_emb, pos_w, pos_q_w, pos_q_b);

    // K3: c2p_raw / p2c_raw (fp16)
    relsc_kernel<<<dim3(S2 / 128, NSEQ / 128, NHEAD * 2), 256, relsc_smem>>>();

    // K4: scores (+ per-tile stats, fp16 probs)
    scores_kernel<<<dim3(NSEQ / 128, NSEQ / 128, NHEAD), 256, scores_smem>>>();

    // K5: combine stats
    combine_kernel<<<(NHEAD * NSEQ) / 256, 256>>>();

    // K6: PV direct to output
    pv_kernel<<<dim3(NSEQ / 128, NHEAD), 256>>>(out);
}

// round 15
// speedup vs baseline: 1.0133x; 1.0133x over previous
#include <cuda_runtime.h>
#include <cuda_fp16.h>
#include <math.h>

#define NSEQ 2048
#define HDIM 1024
#define NHEAD 16
#define DH 64
#define S2 1024        // 2 * span
#define SPAN 512
#define INV_SCALE 0.0721687836487032f   // 1/sqrt(64*3)

// ---------------- scratch (device globals; no allocations allowed) ----------
__device__ __half g_Q[NHEAD * NSEQ * DH];            // fp16 (MMA-native)
__device__ __half g_K[NHEAD * NSEQ * DH];
__device__ __half g_V[NHEAD * NSEQ * DH];
__device__ __half g_PosK[NHEAD * S2 * DH];
__device__ __half g_PosQ[NHEAD * S2 * DH];
__device__ __half g_c2p[(size_t)NHEAD * NSEQ * S2];   // 67 MB (fp16)
__device__ __half g_p2c[(size_t)NHEAD * NSEQ * S2];   // 67 MB (fp16)
__device__ __half g_scH[(size_t)NHEAD * NSEQ * NSEQ]; // 134 MB tile-ref'd exp probs
__device__ unsigned g_maskBits[NSEQ * (NSEQ / 32)];  // 512 KB packed mask
__device__ float g_statM[(size_t)NHEAD * NSEQ * 32]; // per-row per-halftile max
__device__ float g_statL[(size_t)NHEAD * NSEQ * 32]; // per-row per-halftile sumexp
__device__ float g_rowM  [NHEAD * NSEQ];
__device__ float g_rowInv[NHEAD * NSEQ];

// ------------------------------- fp16 mma -----------------------------------
__device__ __forceinline__ unsigned f2h2(float a, float b) {
    __half2 h = __floats2half2_rn(a, b);
    return *reinterpret_cast<unsigned*>(&h);
}

__device__ __forceinline__ unsigned smem_u32(const void* p) {
    return (unsigned)__cvta_generic_to_shared(p);
}

__device__ __forceinline__ void ldsm_x4(unsigned& r0, unsigned& r1,
                                        unsigned& r2, unsigned& r3, unsigned addr) {
    asm volatile("ldmatrix.sync.aligned.m8n8.x4.shared.b16 {%0,%1,%2,%3}, [%4];"
                 : "=r"(r0), "=r"(r1), "=r"(r2), "=r"(r3) : "r"(addr));
}

__device__ __forceinline__ void mma_f16(float (&d)[4],
                                        unsigned a0, unsigned a1, unsigned a2, unsigned a3,
                                        unsigned b0, unsigned b1) {
    asm volatile(
        "mma.sync.aligned.m16n8k16.row.col.f32.f16.f16.f32 "
        "{%0,%1,%2,%3}, {%4,%5,%6,%7}, {%8,%9}, {%0,%1,%2,%3};"
        : "+f"(d[0]), "+f"(d[1]), "+f"(d[2]), "+f"(d[3])
        : "r"(a0), "r"(a1), "r"(a2), "r"(a3), "r"(b0), "r"(b1));
}

// One BK=16 step of m16n8k16, fragments via ldmatrix.x4.
// Operand layout [row][kpair] (half2 packed). Strides ≡4 (mod 8) in 4-byte
// units for conflict-free LDSM (12 and 36 both qualify).
template <int MT, int NT>
__device__ __forceinline__ void mma16(const unsigned* __restrict__ As, int lda,
                                      const unsigned* __restrict__ Bs, int ldb,
                                      int kp0, int wm0, int wn0, int lane,
                                      float (&acc)[MT][NT][4]) {
    const int j = lane >> 3, r = lane & 7;
    unsigned a[MT][4];
#pragma unroll
    for (int mt = 0; mt < MT; mt++) {
        unsigned addr = smem_u32(
            &As[(size_t)(wm0 + mt * 16 + (j & 1) * 8 + r) * lda + kp0 + (j >> 1) * 4]);
        ldsm_x4(a[mt][0], a[mt][1], a[mt][2], a[mt][3], addr);
    }
    unsigned b0[NT], b1[NT];
#pragma unroll
    for (int i = 0; i < NT / 2; i++) {
        unsigned addr = smem_u32(
            &Bs[(size_t)(wn0 + (2 * i + (j >> 1)) * 8 + r) * ldb + kp0 + (j & 1) * 4]);
        ldsm_x4(b0[2 * i], b1[2 * i], b0[2 * i + 1], b1[2 * i + 1], addr);
    }
#pragma unroll
    for (int nt = 0; nt < NT; nt++)
#pragma unroll
        for (int mt = 0; mt < MT; mt++)
            mma_f16(acc[mt][nt], a[mt][0], a[mt][1], a[mt][2], a[mt][3], b0[nt], b1[nt]);
}

// Variant for pv: A via ldmatrix, B via scalar LDS (B stride 13 not LDSM-safe).
template <int NT>
__device__ __forceinline__ void mma16_bs(const unsigned* __restrict__ As, int lda,
                                         const unsigned* __restrict__ Bs, int ldb,
                                         int wm0, int lane,
                                         float (&acc)[1][NT][4]) {
    const int j = lane >> 3, r = lane & 7;
    const int kq = lane & 3, rq = lane >> 2;
    unsigned a[4];
    {
        unsigned addr = smem_u32(
            &As[(size_t)(wm0 + (j & 1) * 8 + r) * lda + (j >> 1) * 4]);
        ldsm_x4(a[0], a[1], a[2], a[3], addr);
    }
#pragma unroll
    for (int nt = 0; nt < NT; nt++) {
        const int n = nt * 8 + rq;
        unsigned b0 = Bs[(size_t)n * ldb + kq];
        unsigned b1 = Bs[(size_t)n * ldb + kq + 4];
        mma_f16(acc[0][nt], a[0], a[1], a[2], a[3], b0, b1);
    }
}

// ---------------------------------------------------------------------------
// K0: pack attention mask into bits
// ---------------------------------------------------------------------------
__global__ void __launch_bounds__(256) pack_kernel(const int* __restrict__ mask) {
    int gid = blockIdx.x * 256 + threadIdx.x;
    unsigned b = __ballot_sync(0xffffffffu, mask[gid] != 0);
    if ((gid & 31) == 0) g_maskBits[gid >> 5] = b;
}

// ---------------------------------------------------------------------------
// K1: QKV projection. M=2048, N=3072, K=1024. BM=BN=128, BK=16, double-buffered.
// ---------------------------------------------------------------------------
#define LDK 12   // 8 kpairs + 4 pad (half2 units); 12 ≡ 4 (mod 8) -> LDSM-safe
__global__ void __launch_bounds__(256) qkv_kernel(const float* __restrict__ hidden,
                                                  const float* __restrict__ W,
                                                  const float* __restrict__ qb,
                                                  const float* __restrict__ vb) {
    __shared__ unsigned As[2][128 * LDK];
    __shared__ unsigned Bs[2][128 * LDK];
    const int t = threadIdx.x, lane = t & 31, wid = t >> 5;
    const int wm0 = (wid >> 1) * 32, wn0 = (wid & 1) * 64;
    const int m0 = blockIdx.y * 128, n0 = blockIdx.x * 128;
    const int r0 = t >> 2, g = t & 3;

    float acc[2][8][4];
#pragma unroll
    for (int mt = 0; mt < 2; mt++)
#pragma unroll
        for (int nt = 0; nt < 8; nt++)
#pragma unroll
            for (int e = 0; e < 4; e++) acc[mt][nt][e] = 0.0f;

    float4 ra[2], rb[2];
    auto ldg = [&](int kt) {
        ra[0] = *(const float4*)&hidden[(size_t)(m0 + r0) * HDIM + kt + g * 4];
        ra[1] = *(const float4*)&hidden[(size_t)(m0 + r0 + 64) * HDIM + kt + g * 4];
        rb[0] = *(const float4*)&W[(size_t)(n0 + r0) * HDIM + kt + g * 4];
        rb[1] = *(const float4*)&W[(size_t)(n0 + r0 + 64) * HDIM + kt + g * 4];
    };
    auto sts = [&](int buf) {
#pragma unroll
        for (int half = 0; half < 2; half++) {
            int r = r0 + half * 64;
            As[buf][r * LDK + g * 2]     = f2h2(((float*)ra)[half * 4 + 0], ((float*)ra)[half * 4 + 1]);
            As[buf][r * LDK + g * 2 + 1] = f2h2(((float*)ra)[half * 4 + 2], ((float*)ra)[half * 4 + 3]);
            Bs[buf][r * LDK + g * 2]     = f2h2(((float*)rb)[half * 4 + 0], ((float*)rb)[half * 4 + 1]);
            Bs[buf][r * LDK + g * 2 + 1] = f2h2(((float*)rb)[half * 4 + 2], ((float*)rb)[half * 4 + 3]);
        }
    };

    ldg(0); sts(0);
    const int nt_tiles = HDIM / 16;
    for (int kt = 0; kt < nt_tiles; kt++) {
        __syncthreads();
        if (kt + 1 < nt_tiles) ldg((kt + 1) * 16);
        mma16<2, 8>(As[kt & 1], LDK, Bs[kt & 1], LDK, 0, wm0, wn0, lane, acc);
        if (kt + 1 < nt_tiles) sts((kt + 1) & 1);
    }

    const int kq = lane & 3, rq = lane >> 2;
#pragma unroll
    for (int mt = 0; mt < 2; mt++)
#pragma unroll
        for (int nt = 0; nt < 8; nt++)
#pragma unroll
            for (int h2 = 0; h2 < 2; h2++) {
                int m  = m0 + wm0 + mt * 16 + rq + h2 * 8;
                int cg = n0 + wn0 + nt * 8 + kq * 2;
                int head = cg / 192;
                int jj = cg - head * 192;
                float v0 = acc[mt][nt][h2 * 2], v1 = acc[mt][nt][h2 * 2 + 1];
                if (jj < 64) {
                    v0 = (v0 + qb[head * 64 + jj]) * INV_SCALE;
                    v1 = (v1 + qb[head * 64 + jj + 1]) * INV_SCALE;
                    *(__half2*)&g_Q[(size_t)(head * NSEQ + m) * DH + jj] =
                        __floats2half2_rn(v0, v1);
                } else if (jj < 128) {
                    *(__half2*)&g_K[(size_t)(head * NSEQ + m) * DH + jj - 64] =
                        __floats2half2_rn(v0, v1);
                } else {
                    v0 += vb[head * 64 + jj - 128];
                    v1 += vb[head * 64 + jj - 127];
                    *(__half2*)&g_V[(size_t)(head * NSEQ + m) * DH + jj - 128] =
                        __floats2half2_rn(v0, v1);
                }
            }
}

// ---------------------------------------------------------------------------
// K2: position projections. z=0: PosK, z=1: PosQ. M=N=K=1024.
// ---------------------------------------------------------------------------
__global__ void __launch_bounds__(256) pos_kernel(const float* __restrict__ rel,
                                                  const float* __restrict__ Wk,
                                                  const float* __restrict__ Wq,
                                                  const float* __restrict__ bias) {
    __shared__ unsigned As[2][128 * LDK];
    __shared__ unsigned Bs[2][128 * LDK];
    const int which = blockIdx.z;
    const float* W = which == 0 ? Wk : Wq;
    const int t = threadIdx.x, lane = t & 31, wid = t >> 5;
    const int wm0 = (wid >> 1) * 32, wn0 = (wid & 1) * 64;
    const int m0 = blockIdx.y * 128, n0 = blockIdx.x * 128;
    const int r0 = t >> 2, g = t & 3;

    float acc[2][8][4];
#pragma unroll
    for (int mt = 0; mt < 2; mt++)
#pragma unroll
        for (int nt = 0; nt < 8; nt++)
#pragma unroll
            for (int e = 0; e < 4; e++) acc[mt][nt][e] = 0.0f;

    float4 ra[2], rb[2];
    auto ldg = [&](int kt) {
        ra[0] = *(const float4*)&rel[(size_t)(m0 + r0) * HDIM + kt + g * 4];
        ra[1] = *(const float4*)&rel[(size_t)(m0 + r0 + 64) * HDIM + kt + g * 4];
        rb[0] = *(const float4*)&W[(size_t)(n0 + r0) * HDIM + kt + g * 4];
        rb[1] = *(const float4*)&W[(size_t)(n0 + r0 + 64) * HDIM + kt + g * 4];
    };
    auto sts = [&](int buf) {
#pragma unroll
        for (int half = 0; half < 2; half++) {
            int r = r0 + half * 64;
            As[buf][r * LDK + g * 2]     = f2h2(((float*)ra)[half * 4 + 0], ((float*)ra)[half * 4 + 1]);
            As[buf][r * LDK + g * 2 + 1] = f2h2(((float*)ra)[half * 4 + 2], ((float*)ra)[half * 4 + 3]);
            Bs[buf][r * LDK + g * 2]     = f2h2(((float*)rb)[half * 4 + 0], ((float*)rb)[half * 4 + 1]);
            Bs[buf][r * LDK + g * 2 + 1] = f2h2(((float*)rb)[half * 4 + 2], ((float*)rb)[half * 4 + 3]);
        }
    };

    ldg(0); sts(0);
    const int nt_tiles = HDIM / 16;
    for (int kt = 0; kt < nt_tiles; kt++) {
        __syncthreads();
        if (kt + 1 < nt_tiles) ldg((kt + 1) * 16);
        mma16<2, 8>(As[kt & 1], LDK, Bs[kt & 1], LDK, 0, wm0, wn0, lane, acc);
        if (kt + 1 < nt_tiles) sts((kt + 1) & 1);
    }

    const int kq = lane & 3, rq = lane >> 2;
#pragma unroll
    for (int mt = 0; mt < 2; mt++)
#pragma unroll
        for (int nt = 0; nt < 8; nt++)
#pragma unroll
            for (int h2 = 0; h2 < 2; h2++) {
                int s  = m0 + wm0 + mt * 16 + rq + h2 * 8;
                int cc = n0 + wn0 + nt * 8 + kq * 2;
                int head = cc >> 6, d = cc & 63;
                float v0 = acc[mt][nt][h2 * 2], v1 = acc[mt][nt][h2 * 2 + 1];
                if (which == 0) {
                    *(__half2*)&g_PosK[(size_t)(head * S2 + s) * DH + d] =
                        __floats2half2_rn(v0, v1);
                } else {
                    v0 = (v0 + bias[cc]) * INV_SCALE;
                    v1 = (v1 + bias[cc + 1]) * INV_SCALE;
                    *(__half2*)&g_PosQ[(size_t)(head * S2 + s) * DH + d] =
                        __floats2half2_rn(v0, v1);
                }
            }
}

// ---------------------------------------------------------------------------
// K=64 tile fill from fp16 source: pure copy into [row][kpair], LDK64=36.
// ---------------------------------------------------------------------------
#define LDK64 36   // 32 kpairs + 4 pad; 36 ≡ 4 (mod 8) -> LDSM-safe
__device__ __forceinline__ void fill_k64h(const __half* __restrict__ src, int row0,
                                          unsigned* __restrict__ T, int t) {
#pragma unroll
    for (int i = 0; i < 4; i++) {
        int lin4 = i * 256 + t;           // 1024 uint4s (128 rows x 8)
        int r = lin4 >> 3, g = lin4 & 7;
        uint4 v = *(const uint4*)&src[(size_t)(row0 + r) * DH + g * 8];
        *(uint4*)&T[r * LDK64 + g * 4] = v;
    }
}

// Staging tile stride (uints): 68 -> STS banks 4*rq + kq, all 32 distinct.
#define LDO 68

// ---------------------------------------------------------------------------
// K3: raw relative scores -> fp16, smem-staged coalesced epilogue.
// 2 CTAs/SM forced (36.9 KB smem, <=128 regs both fit).
// ---------------------------------------------------------------------------
__global__ void __launch_bounds__(256, 2) relsc_kernel() {
    extern __shared__ float sm[];
    unsigned* As = (unsigned*)sm;
    unsigned* Bs = (unsigned*)sm + 128 * LDK64;
    unsigned* Ot = (unsigned*)sm;            // reused after MMA (8704 <= 9216)
    const int z = blockIdx.z;
    const int h = z & 15, which = z >> 4;
    const int m0 = blockIdx.y * 128, n0 = blockIdx.x * 128;
    const __half* A = (which == 0 ? g_Q : g_K) + (size_t)h * NSEQ * DH;
    const __half* B = (which == 0 ? g_PosK : g_PosQ) + (size_t)h * S2 * DH;
    __half* O = (which == 0 ? g_c2p : g_p2c);

    const int t = threadIdx.x, lane = t & 31, wid = t >> 5;
    const int wm0 = (wid >> 1) * 32, wn0 = (wid & 1) * 64;

    fill_k64h(A, m0, As, t);
    fill_k64h(B, n0, Bs, t);
    __syncthreads();

    float acc[2][8][4];
#pragma unroll
    for (int mt = 0; mt < 2; mt++)
#pragma unroll
        for (int nt = 0; nt < 8; nt++)
#pragma unroll
            for (int e = 0; e < 4; e++) acc[mt][nt][e] = 0.0f;

#pragma unroll
    for (int s16 = 0; s16 < 4; s16++)
        mma16<2, 8>(As, LDK64, Bs, LDK64, s16 * 8, wm0, wn0, lane, acc);

    __syncthreads();   // operands consumed -> reuse as staging
    const int kq = lane & 3, rq = lane >> 2;
#pragma unroll
    for (int mt = 0; mt < 2; mt++)
#pragma unroll
        for (int nt = 0; nt < 8; nt++)
#pragma unroll
            for (int h2 = 0; h2 < 2; h2++) {
                int rm = wm0 + mt * 16 + rq + h2 * 8;
                int cn = (wn0 >> 1) + nt * 4 + kq;
                Ot[rm * LDO + cn] = f2h2(acc[mt][nt][h2 * 2], acc[mt][nt][h2 * 2 + 1]);
            }
    __syncthreads();
    // coalesced copy out: 128 rows x 16 uint4
#pragma unroll
    for (int i = 0; i < 8; i++) {
        int lin4 = i * 256 + t;
        int r = lin4 >> 4, c4 = (lin4 & 15) * 4;
        uint4 v = *(const uint4*)&Ot[r * LDO + c4];
        *(uint4*)&O[((size_t)(h * NSEQ + m0 + r)) * S2 + n0 + c4 * 2] = v;
    }
}

// ---------------------------------------------------------------------------
// K4: scores = QK^T + c2p + p2c + mask(bits) -> fp16 exp(s - m_tile) + stats.
// Fast path for fully-clamped tiles; smem-staged coalesced prob store.
// (R12 band path: fp32 G staging — measured best.)
// ---------------------------------------------------------------------------
#define GLD 130
__global__ void __launch_bounds__(256, 2) scores_kernel() {
    extern __shared__ float sm[];
    unsigned* As = (unsigned*)sm;
    unsigned* Bs = (unsigned*)sm + 128 * LDK64;
    float* G  = sm;                          // band path: 128 x 130 fp32
    float* cE = sm + 2 * 128 * LDK64;        // fast path: after As/Bs
    float* pE = cE + 128;
    unsigned* Ot = (unsigned*)(sm + 128 * GLD);   // staging after G

    const int h  = blockIdx.z;
    const int m0 = blockIdx.y * 128, n0 = blockIdx.x * 128;
    const int d  = m0 - n0;
    const bool fast = (d >= 640) || (d <= -640);
    const int t = threadIdx.x, lane = t & 31, wid = t >> 5;
    const int wm0 = (wid >> 1) * 32, wn0 = (wid & 1) * 64;

    const __half* C2 = g_c2p + (size_t)h * NSEQ * S2;
    const __half* P2 = g_p2c + (size_t)h * NSEQ * S2;

    fill_k64h(g_Q + (size_t)h * NSEQ * DH, m0, As, t);
    fill_k64h(g_K + (size_t)h * NSEQ * DH, n0, Bs, t);
    if (fast) {
        const int col = (d >= 640) ? (S2 - 1) : 0;
        if (t < 128) cE[t] = __half2float(C2[(size_t)(m0 + t) * S2 + col]);
        else         pE[t - 128] = __half2float(P2[(size_t)(n0 + t - 128) * S2 + col]);
    }
    __syncthreads();

    float acc[2][8][4];
#pragma unroll
    for (int mt = 0; mt < 2; mt++)
#pragma unroll
        for (int nt = 0; nt < 8; nt++)
#pragma unroll
            for (int e = 0; e < 4; e++) acc[mt][nt][e] = 0.0f;

#pragma unroll
    for (int s16 = 0; s16 < 4; s16++)
        mma16<2, 8>(As, LDK64, Bs, LDK64, s16 * 8, wm0, wn0, lane, acc);

    if (!fast) {
        __syncthreads();   // done with As/Bs -> reuse as G
        // G = c2p tile (coalesced along k-local)
#pragma unroll
        for (int i = 0; i < 64; i++) {
            int lin = i * 256 + t;
            int r = lin >> 7, j = lin & 127;
            int q = m0 + r, kc = n0 + j;
            int idx = q - kc + SPAN;
            idx = idx < 0 ? 0 : (idx > S2 - 1 ? S2 - 1 : idx);
            G[r * GLD + j] = __half2float(C2[(size_t)q * S2 + idx]);
        }
        __syncthreads();
        // G += p2c (global reads coalesced along q, smem writes transposed)
#pragma unroll
        for (int i = 0; i < 64; i++) {
            int lin = i * 256 + t;
            int jr = lin >> 7, qi = lin & 127;
            int kc = n0 + jr, q = m0 + qi;
            int idx = q - kc + SPAN;
            idx = idx < 0 ? 0 : (idx > S2 - 1 ? S2 - 1 : idx);
            G[qi * GLD + jr] += __half2float(P2[(size_t)kc * S2 + idx]);
        }
        __syncthreads();
    }

    // epilogue: finalize, stage fp16 exp(s - m_tile) in smem, per-halftile stats
    const int kq = lane & 3, rq = lane >> 2;
    const int ht = blockIdx.x * 2 + (wn0 >> 6);
    const int wbase = (n0 + wn0) >> 5;
#pragma unroll
    for (int mt = 0; mt < 2; mt++)
#pragma unroll
        for (int h2 = 0; h2 < 2; h2++) {
            const int rm = wm0 + mt * 16 + rq + h2 * 8;
            const int q = m0 + rm;
            const unsigned mwA = g_maskBits[q * (NSEQ / 32) + wbase];
            const unsigned mwB = g_maskBits[q * (NSEQ / 32) + wbase + 1];
            const float ce = fast ? cE[rm] : 0.0f;
            float vals[16];
            float rmax = -INFINITY;
#pragma unroll
            for (int nt = 0; nt < 8; nt++) {
                int rn = wn0 + nt * 8 + kq * 2;
                float b0, b1;
                if (fast) { b0 = ce + pE[rn]; b1 = ce + pE[rn + 1]; }
                else { float2 gb = *(const float2*)&G[rm * GLD + rn];
                       b0 = gb.x; b1 = gb.y; }
                float v0 = acc[mt][nt][h2 * 2]     + b0;
                float v1 = acc[mt][nt][h2 * 2 + 1] + b1;
                unsigned w = (nt < 4) ? mwA : mwB;
                int bp = ((nt & 3) * 8) + kq * 2;
                if (!((w >> bp) & 1u))       v0 = -1e30f;
                if (!((w >> (bp + 1)) & 1u)) v1 = -1e30f;
                vals[nt * 2] = v0; vals[nt * 2 + 1] = v1;
                rmax = fmaxf(rmax, fmaxf(v0, v1));
            }
            rmax = fmaxf(rmax, __shfl_xor_sync(0xffffffffu, rmax, 1));
            rmax = fmaxf(rmax, __shfl_xor_sync(0xffffffffu, rmax, 2));
            float rsum = 0.0f;
#pragma unroll
            for (int nt = 0; nt < 8; nt++) {
                int cn = (wn0 >> 1) + nt * 4 + kq;
                float p0 = __expf(vals[nt * 2] - rmax);
                float p1 = __expf(vals[nt * 2 + 1] - rmax);
                rsum += p0 + p1;
                Ot[rm * LDO + cn] = f2h2(p0, p1);
            }
            rsum += __shfl_xor_sync(0xffffffffu, rsum, 1);
            rsum += __shfl_xor_sync(0xffffffffu, rsum, 2);
            if (kq == 0) {
                g_statM[((size_t)(h * NSEQ + q)) * 32 + ht] = rmax;
                g_statL[((size_t)(h * NSEQ + q)) * 32 + ht] = rsum;
            }
        }
    __syncthreads();
    // coalesced prob store: 128 rows x 16 uint4
#pragma unroll
    for (int i = 0; i < 8; i++) {
        int lin4 = i * 256 + t;
        int r = lin4 >> 4, c4 = (lin4 & 15) * 4;
        uint4 v = *(const uint4*)&Ot[r * LDO + c4];
        *(uint4*)&g_scH[((size_t)(h * NSEQ + m0 + r)) * NSEQ + n0 + c4 * 2] = v;
    }
}

// ---------------------------------------------------------------------------
// K5: combine per-halftile stats into row max / inv-sum
// ---------------------------------------------------------------------------
__global__ void __launch_bounds__(256) combine_kernel() {
    const int row = blockIdx.x * 256 + threadIdx.x;   // h*NSEQ + q
    const size_t b = (size_t)row * 32;
    float m = -INFINITY;
#pragma unroll
    for (int i = 0; i < 32; i++) m = fmaxf(m, g_statM[b + i]);
    float l = 0.0f;
#pragma unroll
    for (int i = 0; i < 32; i++) l += g_statL[b + i] * __expf(g_statM[b + i] - m);
    g_rowM[row]   = m;
    g_rowInv[row] = 1.0f / l;
}

// ---------------------------------------------------------------------------
// K6: PV, full K=2048, direct output write (normalization in corr).
// fp16 probs * per-(row, halftile) corr fused into the A fill.
// A fragments via ldmatrix (LDK=12 LDSM-safe); B scalar (LDKB=13).
// 2 CTAs/SM forced (35 KB smem).
// ---------------------------------------------------------------------------
#define LDKB 13   // B tile: 8 kpairs + 5 pad
__global__ void __launch_bounds__(256, 2) pv_kernel(float* __restrict__ out) {
    __shared__ unsigned As[2][128 * LDK];
    __shared__ unsigned Bs[2][64 * LDKB];
    __shared__ float corr[128 * 32];    // [r][halftile]

    const int mt0 = blockIdx.x, h = blockIdx.y;
    const int m0 = mt0 * 128;
    const int t = threadIdx.x, lane = t & 31, wid = t >> 5;
    const int wm0 = wid * 16;
    const __half* Ag = g_scH + (size_t)h * NSEQ * NSEQ;
    const __half* Vg = g_V + (size_t)h * NSEQ * DH;

    for (int idx = t; idx < 128 * 32; idx += 256) {
        int r = idx >> 5, htl = idx & 31;
        int row = h * NSEQ + m0 + r;
        corr[idx] = __expf(g_statM[(size_t)row * 32 + htl] - g_rowM[row])
                    * g_rowInv[row];
    }
    __syncthreads();

    float acc[1][8][4];
#pragma unroll
    for (int nt = 0; nt < 8; nt++)
#pragma unroll
        for (int e = 0; e < 4; e++) acc[0][nt][e] = 0.0f;

    const int ra0 = t >> 1, ca = t & 1;         // A: 128 rows x 2 uint4/row
    const int kpB = (t >> 3) & 7, d8 = (t & 7) * 8;  // B: 64 active threads
    const bool bact = t < 64;
    uint4 pa, vb0, vb1;
    auto ldg = [&](int kt) {
        pa = *(const uint4*)&Ag[(size_t)(m0 + ra0) * NSEQ + kt + ca * 8];
        if (bact) {
            vb0 = *(const uint4*)&Vg[(size_t)(kt + 2 * kpB) * DH + d8];
            vb1 = *(const uint4*)&Vg[(size_t)(kt + 2 * kpB + 1) * DH + d8];
        }
    };
    auto sts = [&](int buf, int kt_idx) {
        __half2 c2 = __float2half2_rn(corr[ra0 * 32 + (kt_idx >> 2)]);
        const __half2* hp = (const __half2*)&pa;
#pragma unroll
        for (int e = 0; e < 4; e++) {
            __half2 v = __hmul2(hp[e], c2);
            As[buf][ra0 * LDK + ca * 4 + e] = *reinterpret_cast<unsigned*>(&v);
        }
        if (bact) {
            const unsigned* a0 = (const unsigned*)&vb0;
            const unsigned* a1 = (const unsigned*)&vb1;
#pragma unroll
            for (int e = 0; e < 4; e++) {
                Bs[buf][(d8 + 2 * e) * LDKB + kpB]     = __byte_perm(a0[e], a1[e], 0x5410);
                Bs[buf][(d8 + 2 * e + 1) * LDKB + kpB] = __byte_perm(a0[e], a1[e], 0x7632);
            }
        }
    };

    ldg(0); sts(0, 0);
    const int ntile = NSEQ / 16;   // 128
    for (int kt = 0; kt < ntile; kt++) {
        __syncthreads();
        if (kt + 1 < ntile) ldg((kt + 1) * 16);
        mma16_bs<8>(As[kt & 1], LDK, Bs[kt & 1], LDKB, wm0, lane, acc);
        if (kt + 1 < ntile) sts((kt + 1) & 1, kt + 1);
    }

    const int kq = lane & 3, rq = lane >> 2;
#pragma unroll
    for (int nt = 0; nt < 8; nt++)
#pragma unroll
        for (int h2 = 0; h2 < 2; h2++) {
            int m = m0 + wm0 + rq + h2 * 8;
            int n = nt * 8 + kq * 2;
            *(float2*)&out[(size_t)m * HDIM + h * DH + n] =
                make_float2(acc[0][nt][h2 * 2], acc[0][nt][h2 * 2 + 1]);
        }
}

// ---------------------------------------------------------------------------
extern "C" void kernel_launch(void* const* d_in, const int* in_sizes, int n_in,
                              void* d_out, int out_size) {
    const float* hidden   = (const float*)d_in[0];
    const int*   mask     = (const int*)  d_in[1];
    const float* rel_emb  = (const float*)d_in[3];
    const float* in_proj  = (const float*)d_in[4];
    const float* q_bias   = (const float*)d_in[5];
    const float* v_bias   = (const float*)d_in[6];
    const float* pos_w    = (const float*)d_in[7];
    const float* pos_q_w  = (const float*)d_in[8];
    const float* pos_q_b  = (const float*)d_in[9];
    float* out = (float*)d_out;

    const int relsc_smem  = 2 * 128 * LDK64 * 4;             // 36864 B
    const int scores_smem = (128 * GLD + 128 * LDO) * 4;     // 101376 B
    cudaFuncSetAttribute(relsc_kernel, cudaFuncAttributeMaxDynamicSharedMemorySize,
                         relsc_smem);
    cudaFuncSetAttribute(scores_kernel, cudaFuncAttributeMaxDynamicSharedMemorySize,
                         scores_smem);

    // K0: pack mask bits
    pack_kernel<<<(NSEQ * NSEQ) / 256, 256>>>(mask);

    // K1: QKV projection (fp16 outputs)
    qkv_kernel<<<dim3(3072 / 128, 2048 / 128), 256>>>(hidden, in_proj, q_bias, v_bias);

    // K2: position projections (fp16 outputs)
    pos_kernel<<<dim3(HDIM / 128, S2 / 128, 2), 256>>>(rel_emb, pos_w, pos_q_w, pos_q_b);

    // K3: c2p_raw / p2c_raw (fp16)
    relsc_kernel<<<dim3(S2 / 128, NSEQ / 128, NHEAD * 2), 256, relsc_smem>>>();

    // K4: scores (+ per-tile stats, fp16 probs)
    scores_kernel<<<dim3(NSEQ / 128, NSEQ / 128, NHEAD), 256, scores_smem>>>();

    // K5: combine stats
    combine_kernel<<<(NHEAD * NSEQ) / 256, 256>>>();

    // K6: PV direct to output
    pv_kernel<<<dim3(NSEQ / 128, NHEAD), 256>>>(out);
}

// round 16
// speedup vs baseline: 1.0253x; 1.0119x over previous
#include <cuda_runtime.h>
#include <cuda_fp16.h>
#include <math.h>

#define NSEQ 2048
#define HDIM 1024
#define NHEAD 16
#define DH 64
#define S2 1024        // 2 * span
#define SPAN 512
#define INV_SCALE 0.0721687836487032f   // 1/sqrt(64*3)

// ---------------- scratch (device globals; no allocations allowed) ----------
__device__ __half g_hid16[NSEQ * HDIM];              // fp16 copies of inputs
__device__ __half g_w16[3 * HDIM * HDIM];
__device__ __half g_rel16[S2 * HDIM];
__device__ __half g_wk16[HDIM * HDIM];
__device__ __half g_wq16[HDIM * HDIM];
__device__ __half g_Q[NHEAD * NSEQ * DH];            // fp16 (MMA-native)
__device__ __half g_K[NHEAD * NSEQ * DH];
__device__ __half g_V[NHEAD * NSEQ * DH];
__device__ __half g_PosK[NHEAD * S2 * DH];
__device__ __half g_PosQ[NHEAD * S2 * DH];
__device__ __half g_c2p[(size_t)NHEAD * NSEQ * S2];   // 67 MB (fp16)
__device__ __half g_p2c[(size_t)NHEAD * NSEQ * S2];   // 67 MB (fp16)
__device__ __half g_scH[(size_t)NHEAD * NSEQ * NSEQ]; // 134 MB tile-ref'd exp probs
__device__ unsigned g_maskBits[NSEQ * (NSEQ / 32)];  // 512 KB packed mask
__device__ float g_statM[(size_t)NHEAD * NSEQ * 32]; // per-row per-halftile max
__device__ float g_statL[(size_t)NHEAD * NSEQ * 32]; // per-row per-halftile sumexp
__device__ float g_rowM  [NHEAD * NSEQ];
__device__ float g_rowInv[NHEAD * NSEQ];

// ------------------------------- fp16 mma -----------------------------------
__device__ __forceinline__ unsigned f2h2(float a, float b) {
    __half2 h = __floats2half2_rn(a, b);
    return *reinterpret_cast<unsigned*>(&h);
}

__device__ __forceinline__ unsigned smem_u32(const void* p) {
    return (unsigned)__cvta_generic_to_shared(p);
}

__device__ __forceinline__ void ldsm_x4(unsigned& r0, unsigned& r1,
                                        unsigned& r2, unsigned& r3, unsigned addr) {
    asm volatile("ldmatrix.sync.aligned.m8n8.x4.shared.b16 {%0,%1,%2,%3}, [%4];"
                 : "=r"(r0), "=r"(r1), "=r"(r2), "=r"(r3) : "r"(addr));
}

__device__ __forceinline__ void mma_f16(float (&d)[4],
                                        unsigned a0, unsigned a1, unsigned a2, unsigned a3,
                                        unsigned b0, unsigned b1) {
    asm volatile(
        "mma.sync.aligned.m16n8k16.row.col.f32.f16.f16.f32 "
        "{%0,%1,%2,%3}, {%4,%5,%6,%7}, {%8,%9}, {%0,%1,%2,%3};"
        : "+f"(d[0]), "+f"(d[1]), "+f"(d[2]), "+f"(d[3])
        : "r"(a0), "r"(a1), "r"(a2), "r"(a3), "r"(b0), "r"(b1));
}

// One BK=16 step of m16n8k16, fragments via ldmatrix.x4.
// Operand layout [row][kpair] (half2 packed). Strides ≡4 (mod 8) in 4-byte
// units for conflict-free LDSM (12 and 36 both qualify).
template <int MT, int NT>
__device__ __forceinline__ void mma16(const unsigned* __restrict__ As, int lda,
                                      const unsigned* __restrict__ Bs, int ldb,
                                      int kp0, int wm0, int wn0, int lane,
                                      float (&acc)[MT][NT][4]) {
    const int j = lane >> 3, r = lane & 7;
    unsigned a[MT][4];
#pragma unroll
    for (int mt = 0; mt < MT; mt++) {
        unsigned addr = smem_u32(
            &As[(size_t)(wm0 + mt * 16 + (j & 1) * 8 + r) * lda + kp0 + (j >> 1) * 4]);
        ldsm_x4(a[mt][0], a[mt][1], a[mt][2], a[mt][3], addr);
    }
    unsigned b0[NT], b1[NT];
#pragma unroll
    for (int i = 0; i < NT / 2; i++) {
        unsigned addr = smem_u32(
            &Bs[(size_t)(wn0 + (2 * i + (j >> 1)) * 8 + r) * ldb + kp0 + (j & 1) * 4]);
        ldsm_x4(b0[2 * i], b1[2 * i], b0[2 * i + 1], b1[2 * i + 1], addr);
    }
#pragma unroll
    for (int nt = 0; nt < NT; nt++)
#pragma unroll
        for (int mt = 0; mt < MT; mt++)
            mma_f16(acc[mt][nt], a[mt][0], a[mt][1], a[mt][2], a[mt][3], b0[nt], b1[nt]);
}

// Variant for pv: A via ldmatrix, B via scalar LDS (B stride 13 not LDSM-safe).
template <int NT>
__device__ __forceinline__ void mma16_bs(const unsigned* __restrict__ As, int lda,
                                         const unsigned* __restrict__ Bs, int ldb,
                                         int wm0, int lane,
                                         float (&acc)[1][NT][4]) {
    const int j = lane >> 3, r = lane & 7;
    const int kq = lane & 3, rq = lane >> 2;
    unsigned a[4];
    {
        unsigned addr = smem_u32(
            &As[(size_t)(wm0 + (j & 1) * 8 + r) * lda + (j >> 1) * 4]);
        ldsm_x4(a[0], a[1], a[2], a[3], addr);
    }
#pragma unroll
    for (int nt = 0; nt < NT; nt++) {
        const int n = nt * 8 + rq;
        unsigned b0 = Bs[(size_t)n * ldb + kq];
        unsigned b1 = Bs[(size_t)n * ldb + kq + 4];
        mma_f16(acc[0][nt], a[0], a[1], a[2], a[3], b0, b1);
    }
}

// ---------------------------------------------------------------------------
// K-1: fp32 -> fp16 conversion (n must be multiple of 1024)
// ---------------------------------------------------------------------------
__global__ void __launch_bounds__(256) cvt_kernel(const float* __restrict__ src,
                                                  __half* __restrict__ dst) {
    int gid = blockIdx.x * 256 + threadIdx.x;
    float4 v = *(const float4*)&src[(size_t)gid * 4];
    uint2 o;
    o.x = f2h2(v.x, v.y);
    o.y = f2h2(v.z, v.w);
    *(uint2*)&dst[(size_t)gid * 4] = o;
}

// ---------------------------------------------------------------------------
// K0: pack attention mask into bits
// ---------------------------------------------------------------------------
__global__ void __launch_bounds__(256) pack_kernel(const int* __restrict__ mask) {
    int gid = blockIdx.x * 256 + threadIdx.x;
    unsigned b = __ballot_sync(0xffffffffu, mask[gid] != 0);
    if ((gid & 31) == 0) g_maskBits[gid >> 5] = b;
}

// ---------------------------------------------------------------------------
// K1: QKV projection from fp16 inputs. M=2048, N=3072, K=1024.
// BM=BN=128, BK=16, double-buffered; fills are pure uint4 copies.
// ---------------------------------------------------------------------------
#define LDK 12   // 8 kpairs + 4 pad (half2 units); 12 ≡ 4 (mod 8) -> LDSM-safe
__global__ void __launch_bounds__(256) qkv_kernel(const float* __restrict__ qb,
                                                  const float* __restrict__ vb) {
    __shared__ unsigned As[2][128 * LDK];
    __shared__ unsigned Bs[2][128 * LDK];
    const int t = threadIdx.x, lane = t & 31, wid = t >> 5;
    const int wm0 = (wid >> 1) * 32, wn0 = (wid & 1) * 64;
    const int m0 = blockIdx.y * 128, n0 = blockIdx.x * 128;
    const int rr = t >> 1, hh = t & 1;

    float acc[2][8][4];
#pragma unroll
    for (int mt = 0; mt < 2; mt++)
#pragma unroll
        for (int nt = 0; nt < 8; nt++)
#pragma unroll
            for (int e = 0; e < 4; e++) acc[mt][nt][e] = 0.0f;

    uint4 pa, pb;
    auto ldg = [&](int kt) {
        pa = *(const uint4*)&g_hid16[(size_t)(m0 + rr) * HDIM + kt + hh * 8];
        pb = *(const uint4*)&g_w16[(size_t)(n0 + rr) * HDIM + kt + hh * 8];
    };
    auto sts = [&](int buf) {
        *(uint4*)&As[buf][rr * LDK + hh * 4] = pa;
        *(uint4*)&Bs[buf][rr * LDK + hh * 4] = pb;
    };

    ldg(0); sts(0);
    const int nt_tiles = HDIM / 16;
    for (int kt = 0; kt < nt_tiles; kt++) {
        __syncthreads();
        if (kt + 1 < nt_tiles) ldg((kt + 1) * 16);
        mma16<2, 8>(As[kt & 1], LDK, Bs[kt & 1], LDK, 0, wm0, wn0, lane, acc);
        if (kt + 1 < nt_tiles) sts((kt + 1) & 1);
    }

    const int kq = lane & 3, rq = lane >> 2;
#pragma unroll
    for (int mt = 0; mt < 2; mt++)
#pragma unroll
        for (int nt = 0; nt < 8; nt++)
#pragma unroll
            for (int h2 = 0; h2 < 2; h2++) {
                int m  = m0 + wm0 + mt * 16 + rq + h2 * 8;
                int cg = n0 + wn0 + nt * 8 + kq * 2;
                int head = cg / 192;
                int jj = cg - head * 192;
                float v0 = acc[mt][nt][h2 * 2], v1 = acc[mt][nt][h2 * 2 + 1];
                if (jj < 64) {
                    v0 = (v0 + qb[head * 64 + jj]) * INV_SCALE;
                    v1 = (v1 + qb[head * 64 + jj + 1]) * INV_SCALE;
                    *(__half2*)&g_Q[(size_t)(head * NSEQ + m) * DH + jj] =
                        __floats2half2_rn(v0, v1);
                } else if (jj < 128) {
                    *(__half2*)&g_K[(size_t)(head * NSEQ + m) * DH + jj - 64] =
                        __floats2half2_rn(v0, v1);
                } else {
                    v0 += vb[head * 64 + jj - 128];
                    v1 += vb[head * 64 + jj - 127];
                    *(__half2*)&g_V[(size_t)(head * NSEQ + m) * DH + jj - 128] =
                        __floats2half2_rn(v0, v1);
                }
            }
}

// ---------------------------------------------------------------------------
// K2: position projections from fp16 inputs. z=0: PosK, z=1: PosQ.
// ---------------------------------------------------------------------------
__global__ void __launch_bounds__(256) pos_kernel(const float* __restrict__ bias) {
    __shared__ unsigned As[2][128 * LDK];
    __shared__ unsigned Bs[2][128 * LDK];
    const int which = blockIdx.z;
    const __half* W = which == 0 ? g_wk16 : g_wq16;
    const int t = threadIdx.x, lane = t & 31, wid = t >> 5;
    const int wm0 = (wid >> 1) * 32, wn0 = (wid & 1) * 64;
    const int m0 = blockIdx.y * 128, n0 = blockIdx.x * 128;
    const int rr = t >> 1, hh = t & 1;

    float acc[2][8][4];
#pragma unroll
    for (int mt = 0; mt < 2; mt++)
#pragma unroll
        for (int nt = 0; nt < 8; nt++)
#pragma unroll
            for (int e = 0; e < 4; e++) acc[mt][nt][e] = 0.0f;

    uint4 pa, pb;
    auto ldg = [&](int kt) {
        pa = *(const uint4*)&g_rel16[(size_t)(m0 + rr) * HDIM + kt + hh * 8];
        pb = *(const uint4*)&W[(size_t)(n0 + rr) * HDIM + kt + hh * 8];
    };
    auto sts = [&](int buf) {
        *(uint4*)&As[buf][rr * LDK + hh * 4] = pa;
        *(uint4*)&Bs[buf][rr * LDK + hh * 4] = pb;
    };

    ldg(0); sts(0);
    const int nt_tiles = HDIM / 16;
    for (int kt = 0; kt < nt_tiles; kt++) {
        __syncthreads();
        if (kt + 1 < nt_tiles) ldg((kt + 1) * 16);
        mma16<2, 8>(As[kt & 1], LDK, Bs[kt & 1], LDK, 0, wm0, wn0, lane, acc);
        if (kt + 1 < nt_tiles) sts((kt + 1) & 1);
    }

    const int kq = lane & 3, rq = lane >> 2;
#pragma unroll
    for (int mt = 0; mt < 2; mt++)
#pragma unroll
        for (int nt = 0; nt < 8; nt++)
#pragma unroll
            for (int h2 = 0; h2 < 2; h2++) {
                int s  = m0 + wm0 + mt * 16 + rq + h2 * 8;
                int cc = n0 + wn0 + nt * 8 + kq * 2;
                int head = cc >> 6, d = cc & 63;
                float v0 = acc[mt][nt][h2 * 2], v1 = acc[mt][nt][h2 * 2 + 1];
                if (which == 0) {
                    *(__half2*)&g_PosK[(size_t)(head * S2 + s) * DH + d] =
                        __floats2half2_rn(v0, v1);
                } else {
                    v0 = (v0 + bias[cc]) * INV_SCALE;
                    v1 = (v1 + bias[cc + 1]) * INV_SCALE;
                    *(__half2*)&g_PosQ[(size_t)(head * S2 + s) * DH + d] =
                        __floats2half2_rn(v0, v1);
                }
            }
}

// ---------------------------------------------------------------------------
// K=64 tile fill from fp16 source: pure copy into [row][kpair], LDK64=36.
// ---------------------------------------------------------------------------
#define LDK64 36   // 32 kpairs + 4 pad; 36 ≡ 4 (mod 8) -> LDSM-safe
__device__ __forceinline__ void fill_k64h(const __half* __restrict__ src, int row0,
                                          unsigned* __restrict__ T, int t) {
#pragma unroll
    for (int i = 0; i < 4; i++) {
        int lin4 = i * 256 + t;           // 1024 uint4s (128 rows x 8)
        int r = lin4 >> 3, g = lin4 & 7;
        uint4 v = *(const uint4*)&src[(size_t)(row0 + r) * DH + g * 8];
        *(uint4*)&T[r * LDK64 + g * 4] = v;
    }
}

// Staging tile stride (uints): 68 -> STS banks 4*rq + kq, all 32 distinct.
#define LDO 68

// ---------------------------------------------------------------------------
// K3: raw relative scores -> fp16, smem-staged coalesced epilogue.
// ---------------------------------------------------------------------------
__global__ void __launch_bounds__(256) relsc_kernel() {
    extern __shared__ float sm[];
    unsigned* As = (unsigned*)sm;
    unsigned* Bs = (unsigned*)sm + 128 * LDK64;
    unsigned* Ot = (unsigned*)sm;            // reused after MMA (8704 <= 9216)
    const int z = blockIdx.z;
    const int h = z & 15, which = z >> 4;
    const int m0 = blockIdx.y * 128, n0 = blockIdx.x * 128;
    const __half* A = (which == 0 ? g_Q : g_K) + (size_t)h * NSEQ * DH;
    const __half* B = (which == 0 ? g_PosK : g_PosQ) + (size_t)h * S2 * DH;
    __half* O = (which == 0 ? g_c2p : g_p2c);

    const int t = threadIdx.x, lane = t & 31, wid = t >> 5;
    const int wm0 = (wid >> 1) * 32, wn0 = (wid & 1) * 64;

    fill_k64h(A, m0, As, t);
    fill_k64h(B, n0, Bs, t);
    __syncthreads();

    float acc[2][8][4];
#pragma unroll
    for (int mt = 0; mt < 2; mt++)
#pragma unroll
        for (int nt = 0; nt < 8; nt++)
#pragma unroll
            for (int e = 0; e < 4; e++) acc[mt][nt][e] = 0.0f;

#pragma unroll
    for (int s16 = 0; s16 < 4; s16++)
        mma16<2, 8>(As, LDK64, Bs, LDK64, s16 * 8, wm0, wn0, lane, acc);

    __syncthreads();   // operands consumed -> reuse as staging
    const int kq = lane & 3, rq = lane >> 2;
#pragma unroll
    for (int mt = 0; mt < 2; mt++)
#pragma unroll
        for (int nt = 0; nt < 8; nt++)
#pragma unroll
            for (int h2 = 0; h2 < 2; h2++) {
                int rm = wm0 + mt * 16 + rq + h2 * 8;
                int cn = (wn0 >> 1) + nt * 4 + kq;
                Ot[rm * LDO + cn] = f2h2(acc[mt][nt][h2 * 2], acc[mt][nt][h2 * 2 + 1]);
            }
    __syncthreads();
    // coalesced copy out: 128 rows x 16 uint4
#pragma unroll
    for (int i = 0; i < 8; i++) {
        int lin4 = i * 256 + t;
        int r = lin4 >> 4, c4 = (lin4 & 15) * 4;
        uint4 v = *(const uint4*)&Ot[r * LDO + c4];
        *(uint4*)&O[((size_t)(h * NSEQ + m0 + r)) * S2 + n0 + c4 * 2] = v;
    }
}

// ---------------------------------------------------------------------------
// K4: scores = QK^T + c2p + p2c + mask(bits) -> fp16 exp(s - m_tile) + stats.
// Fast path for fully-clamped tiles; smem-staged coalesced prob store.
// ---------------------------------------------------------------------------
#define GLD 130
__global__ void __launch_bounds__(256, 2) scores_kernel() {
    extern __shared__ float sm[];
    unsigned* As = (unsigned*)sm;
    unsigned* Bs = (unsigned*)sm + 128 * LDK64;
    float* G  = sm;                          // band path: 128 x 130 fp32
    float* cE = sm + 2 * 128 * LDK64;        // fast path: after As/Bs
    float* pE = cE + 128;
    unsigned* Ot = (unsigned*)(sm + 128 * GLD);   // staging after G

    const int h  = blockIdx.z;
    const int m0 = blockIdx.y * 128, n0 = blockIdx.x * 128;
    const int d  = m0 - n0;
    const bool fast = (d >= 640) || (d <= -640);
    const int t = threadIdx.x, lane = t & 31, wid = t >> 5;
    const int wm0 = (wid >> 1) * 32, wn0 = (wid & 1) * 64;

    const __half* C2 = g_c2p + (size_t)h * NSEQ * S2;
    const __half* P2 = g_p2c + (size_t)h * NSEQ * S2;

    fill_k64h(g_Q + (size_t)h * NSEQ * DH, m0, As, t);
    fill_k64h(g_K + (size_t)h * NSEQ * DH, n0, Bs, t);
    if (fast) {
        const int col = (d >= 640) ? (S2 - 1) : 0;
        if (t < 128) cE[t] = __half2float(C2[(size_t)(m0 + t) * S2 + col]);
        else         pE[t - 128] = __half2float(P2[(size_t)(n0 + t - 128) * S2 + col]);
    }
    __syncthreads();

    float acc[2][8][4];
#pragma unroll
    for (int mt = 0; mt < 2; mt++)
#pragma unroll
        for (int nt = 0; nt < 8; nt++)
#pragma unroll
            for (int e = 0; e < 4; e++) acc[mt][nt][e] = 0.0f;

#pragma unroll
    for (int s16 = 0; s16 < 4; s16++)
        mma16<2, 8>(As, LDK64, Bs, LDK64, s16 * 8, wm0, wn0, lane, acc);

    if (!fast) {
        __syncthreads();   // done with As/Bs -> reuse as G
        // G = c2p tile (coalesced along k-local)
#pragma unroll
        for (int i = 0; i < 64; i++) {
            int lin = i * 256 + t;
            int r = lin >> 7, j = lin & 127;
            int q = m0 + r, kc = n0 + j;
            int idx = q - kc + SPAN;
            idx = idx < 0 ? 0 : (idx > S2 - 1 ? S2 - 1 : idx);
            G[r * GLD + j] = __half2float(C2[(size_t)q * S2 + idx]);
        }
        __syncthreads();
        // G += p2c (global reads coalesced along q, smem writes transposed)
#pragma unroll
        for (int i = 0; i < 64; i++) {
            int lin = i * 256 + t;
            int jr = lin >> 7, qi = lin & 127;
            int kc = n0 + jr, q = m0 + qi;
            int idx = q - kc + SPAN;
            idx = idx < 0 ? 0 : (idx > S2 - 1 ? S2 - 1 : idx);
            G[qi * GLD + jr] += __half2float(P2[(size_t)kc * S2 + idx]);
        }
        __syncthreads();
    }

    // epilogue: finalize, stage fp16 exp(s - m_tile) in smem, per-halftile stats
    const int kq = lane & 3, rq = lane >> 2;
    const int ht = blockIdx.x * 2 + (wn0 >> 6);
    const int wbase = (n0 + wn0) >> 5;
#pragma unroll
    for (int mt = 0; mt < 2; mt++)
#pragma unroll
        for (int h2 = 0; h2 < 2; h2++) {
            const int rm = wm0 + mt * 16 + rq + h2 * 8;
            const int q = m0 + rm;
            const unsigned mwA = g_maskBits[q * (NSEQ / 32) + wbase];
            const unsigned mwB = g_maskBits[q * (NSEQ / 32) + wbase + 1];
            const float ce = fast ? cE[rm] : 0.0f;
            float vals[16];
            float rmax = -INFINITY;
#pragma unroll
            for (int nt = 0; nt < 8; nt++) {
                int rn = wn0 + nt * 8 + kq * 2;
                float b0, b1;
                if (fast) { b0 = ce + pE[rn]; b1 = ce + pE[rn + 1]; }
                else { float2 gb = *(const float2*)&G[rm * GLD + rn];
                       b0 = gb.x; b1 = gb.y; }
                float v0 = acc[mt][nt][h2 * 2]     + b0;
                float v1 = acc[mt][nt][h2 * 2 + 1] + b1;
                unsigned w = (nt < 4) ? mwA : mwB;
                int bp = ((nt & 3) * 8) + kq * 2;
                if (!((w >> bp) & 1u))       v0 = -1e30f;
                if (!((w >> (bp + 1)) & 1u)) v1 = -1e30f;
                vals[nt * 2] = v0; vals[nt * 2 + 1] = v1;
                rmax = fmaxf(rmax, fmaxf(v0, v1));
            }
            rmax = fmaxf(rmax, __shfl_xor_sync(0xffffffffu, rmax, 1));
            rmax = fmaxf(rmax, __shfl_xor_sync(0xffffffffu, rmax, 2));
            float rsum = 0.0f;
#pragma unroll
            for (int nt = 0; nt < 8; nt++) {
                int cn = (wn0 >> 1) + nt * 4 + kq;
                float p0 = __expf(vals[nt * 2] - rmax);
                float p1 = __expf(vals[nt * 2 + 1] - rmax);
                rsum += p0 + p1;
                Ot[rm * LDO + cn] = f2h2(p0, p1);
            }
            rsum += __shfl_xor_sync(0xffffffffu, rsum, 1);
            rsum += __shfl_xor_sync(0xffffffffu, rsum, 2);
            if (kq == 0) {
                g_statM[((size_t)(h * NSEQ + q)) * 32 + ht] = rmax;
                g_statL[((size_t)(h * NSEQ + q)) * 32 + ht] = rsum;
            }
        }
    __syncthreads();
    // coalesced prob store: 128 rows x 16 uint4
#pragma unroll
    for (int i = 0; i < 8; i++) {
        int lin4 = i * 256 + t;
        int r = lin4 >> 4, c4 = (lin4 & 15) * 4;
        uint4 v = *(const uint4*)&Ot[r * LDO + c4];
        *(uint4*)&g_scH[((size_t)(h * NSEQ + m0 + r)) * NSEQ + n0 + c4 * 2] = v;
    }
}

// ---------------------------------------------------------------------------
// K5: combine per-halftile stats into row max / inv-sum
// ---------------------------------------------------------------------------
__global__ void __launch_bounds__(256) combine_kernel() {
    const int row = blockIdx.x * 256 + threadIdx.x;   // h*NSEQ + q
    const size_t b = (size_t)row * 32;
    float m = -INFINITY;
#pragma unroll
    for (int i = 0; i < 32; i++) m = fmaxf(m, g_statM[b + i]);
    float l = 0.0f;
#pragma unroll
    for (int i = 0; i < 32; i++) l += g_statL[b + i] * __expf(g_statM[b + i] - m);
    g_rowM[row]   = m;
    g_rowInv[row] = 1.0f / l;
}

// ---------------------------------------------------------------------------
// K6: PV, full K=2048, direct output write (normalization in corr).
// fp16 probs * per-(row, halftile) corr fused into the A fill.
// A fragments via ldmatrix (LDK=12 LDSM-safe); B scalar (LDKB=13).
// ---------------------------------------------------------------------------
#define LDKB 13   // B tile: 8 kpairs + 5 pad
__global__ void __launch_bounds__(256) pv_kernel(float* __restrict__ out) {
    __shared__ unsigned As[2][128 * LDK];
    __shared__ unsigned Bs[2][64 * LDKB];
    __shared__ float corr[128 * 32];    // [r][halftile]

    const int mt0 = blockIdx.x, h = blockIdx.y;
    const int m0 = mt0 * 128;
    const int t = threadIdx.x, lane = t & 31, wid = t >> 5;
    const int wm0 = wid * 16;
    const __half* Ag = g_scH + (size_t)h * NSEQ * NSEQ;
    const __half* Vg = g_V + (size_t)h * NSEQ * DH;

    for (int idx = t; idx < 128 * 32; idx += 256) {
        int r = idx >> 5, htl = idx & 31;
        int row = h * NSEQ + m0 + r;
        corr[idx] = __expf(g_statM[(size_t)row * 32 + htl] - g_rowM[row])
                    * g_rowInv[row];
    }
    __syncthreads();

    float acc[1][8][4];
#pragma unroll
    for (int nt = 0; nt < 8; nt++)
#pragma unroll
        for (int e = 0; e < 4; e++) acc[0][nt][e] = 0.0f;

    const int ra0 = t >> 1, ca = t & 1;         // A: 128 rows x 2 uint4/row
    const int kpB = (t >> 3) & 7, d8 = (t & 7) * 8;  // B: 64 active threads
    const bool bact = t < 64;
    uint4 pa, vb0, vb1;
    auto ldg = [&](int kt) {
        pa = *(const uint4*)&Ag[(size_t)(m0 + ra0) * NSEQ + kt + ca * 8];
        if (bact) {
            vb0 = *(const uint4*)&Vg[(size_t)(kt + 2 * kpB) * DH + d8];
            vb1 = *(const uint4*)&Vg[(size_t)(kt + 2 * kpB + 1) * DH + d8];
        }
    };
    auto sts = [&](int buf, int kt_idx) {
        __half2 c2 = __float2half2_rn(corr[ra0 * 32 + (kt_idx >> 2)]);
        const __half2* hp = (const __half2*)&pa;
#pragma unroll
        for (int e = 0; e < 4; e++) {
            __half2 v = __hmul2(hp[e], c2);
            As[buf][ra0 * LDK + ca * 4 + e] = *reinterpret_cast<unsigned*>(&v);
        }
        if (bact) {
            const unsigned* a0 = (const unsigned*)&vb0;
            const unsigned* a1 = (const unsigned*)&vb1;
#pragma unroll
            for (int e = 0; e < 4; e++) {
                Bs[buf][(d8 + 2 * e) * LDKB + kpB]     = __byte_perm(a0[e], a1[e], 0x5410);
                Bs[buf][(d8 + 2 * e + 1) * LDKB + kpB] = __byte_perm(a0[e], a1[e], 0x7632);
            }
        }
    };

    ldg(0); sts(0, 0);
    const int ntile = NSEQ / 16;   // 128
    for (int kt = 0; kt < ntile; kt++) {
        __syncthreads();
        if (kt + 1 < ntile) ldg((kt + 1) * 16);
        mma16_bs<8>(As[kt & 1], LDK, Bs[kt & 1], LDKB, wm0, lane, acc);
        if (kt + 1 < ntile) sts((kt + 1) & 1, kt + 1);
    }

    const int kq = lane & 3, rq = lane >> 2;
#pragma unroll
    for (int nt = 0; nt < 8; nt++)
#pragma unroll
        for (int h2 = 0; h2 < 2; h2++) {
            int m = m0 + wm0 + rq + h2 * 8;
            int n = nt * 8 + kq * 2;
            *(float2*)&out[(size_t)m * HDIM + h * DH + n] =
                make_float2(acc[0][nt][h2 * 2], acc[0][nt][h2 * 2 + 1]);
        }
}

// ---------------------------------------------------------------------------
extern "C" void kernel_launch(void* const* d_in, const int* in_sizes, int n_in,
                              void* d_out, int out_size) {
    const float* hidden   = (const float*)d_in[0];
    const int*   mask     = (const int*)  d_in[1];
    const float* rel_emb  = (const float*)d_in[3];
    const float* in_proj  = (const float*)d_in[4];
    const float* q_bias   = (const float*)d_in[5];
    const float* v_bias   = (const float*)d_in[6];
    const float* pos_w    = (const float*)d_in[7];
    const float* pos_q_w  = (const float*)d_in[8];
    const float* pos_q_b  = (const float*)d_in[9];
    float* out = (float*)d_out;

    const int relsc_smem  = 2 * 128 * LDK64 * 4;             // 36864 B
    const int scores_smem = (128 * GLD + 128 * LDO) * 4;     // 101376 B
    cudaFuncSetAttribute(relsc_kernel, cudaFuncAttributeMaxDynamicSharedMemorySize,
                         relsc_smem);
    cudaFuncSetAttribute(scores_kernel, cudaFuncAttributeMaxDynamicSharedMemorySize,
                         scores_smem);

    __half* d_hid16; cudaGetSymbolAddress((void**)&d_hid16, g_hid16);
    __half* d_w16;   cudaGetSymbolAddress((void**)&d_w16, g_w16);
    __half* d_rel16; cudaGetSymbolAddress((void**)&d_rel16, g_rel16);
    __half* d_wk16;  cudaGetSymbolAddress((void**)&d_wk16, g_wk16);
    __half* d_wq16;  cudaGetSymbolAddress((void**)&d_wq16, g_wq16);

    // K-1: input conversions (fp32 -> fp16, rounding identical to prior fills)
    cvt_kernel<<<(NSEQ * HDIM) / 1024, 256>>>(hidden, d_hid16);
    cvt_kernel<<<(3 * HDIM * HDIM) / 1024, 256>>>(in_proj, d_w16);
    cvt_kernel<<<(S2 * HDIM) / 1024, 256>>>(rel_emb, d_rel16);
    cvt_kernel<<<(HDIM * HDIM) / 1024, 256>>>(pos_w, d_wk16);
    cvt_kernel<<<(HDIM * HDIM) / 1024, 256>>>(pos_q_w, d_wq16);

    // K0: pack mask bits
    pack_kernel<<<(NSEQ * NSEQ) / 256, 256>>>(mask);

    // K1: QKV projection (fp16 in/out)
    qkv_kernel<<<dim3(3072 / 128, 2048 / 128), 256>>>(q_bias, v_bias);

    // K2: position projections (fp16 in/out)
    pos_kernel<<<dim3(HDIM / 128, S2 / 128, 2), 256>>>(pos_q_b);

    // K3: c2p_raw / p2c_raw (fp16)
    relsc_kernel<<<dim3(S2 / 128, NSEQ / 128, NHEAD * 2), 256, relsc_smem>>>();

    // K4: scores (+ per-tile stats, fp16 probs)
    scores_kernel<<<dim3(NSEQ / 128, NSEQ / 128, NHEAD), 256, scores_smem>>>();

    // K5: combine stats
    combine_kernel<<<(NHEAD * NSEQ) / 256, 256>>>();

    // K6: PV direct to output
    pv_kernel<<<dim3(NSEQ / 128, NHEAD), 256>>>(out);
}